// round 15
// baseline (speedup 1.0000x reference)
#include <cuda_runtime.h>
#include <math.h>
#include <stdint.h>

#define Bn 4
#define Tn 8192
#define Dn 1024
#define Hn 8
#define HDn 128
#define Cn 64
#define Nchunk 128
#define BTn (Bn*Tn)
#define BHn (Bn*Hn)
#define WPM 524288                        // words per 1024x1024 matrix (bf16x2)

// ---------------- scratch (device globals; no cudaMalloc allowed) ----------
__device__ float g_v[(size_t)BTn*Dn];       // v*beta -> v' (in place)
__device__ float g_rk[(size_t)BTn*Dn];      // normalized read keys, (B,H,T,d)
__device__ float g_wkcd[(size_t)BTn*Dn];    // wk_cumdecay, (B,H,T,d)
__device__ float g_attn[(size_t)BHn*Nchunk*Cn*Cn];
__device__ float g_beta[BHn*Tn];
__device__ float g_gate[BHn*Tn];
__device__ float g_dec[BHn*Tn];
// bf16x2 hi/lo planes (word = packed pair of adjacent K elements)
__device__ uint32_t g_xh[(size_t)BTn*512];  // x hi
__device__ uint32_t g_xl[(size_t)BTn*512];  // x lo
__device__ uint32_t g_oh[(size_t)BTn*512];  // gated o hi
__device__ uint32_t g_ol[(size_t)BTn*512];  // gated o lo
__device__ uint32_t g_wbh[2*WPM];           // Ww, Wo hi
__device__ uint32_t g_wbl[2*WPM];           // Ww, Wo lo

__device__ __forceinline__ float warp_sum(float v) {
#pragma unroll
  for (int o = 16; o > 0; o >>= 1) v += __shfl_xor_sync(0xffffffffu, v, o);
  return v;
}

// ======================= mma.sync helpers ===================================
__device__ __forceinline__ uint32_t smem_u32(const void* p) {
  uint32_t a;
  asm("{ .reg .u64 t; cvta.to.shared.u64 t, %1; cvt.u32.u64 %0, t; }"
      : "=r"(a) : "l"(p));
  return a;
}

__device__ __forceinline__ uint32_t tf32u(float a) {
  uint32_t r; asm("cvt.rna.tf32.f32 %0, %1;" : "=r"(r) : "f"(a)); return r;
}

__device__ __forceinline__ void split2(float x, uint32_t& hi, uint32_t& lo) {
  hi = tf32u(x);
  lo = tf32u(x - __uint_as_float(hi));
}

__device__ __forceinline__ void mma_tf32(float* c, const uint32_t* a,
                                         const uint32_t* b) {
  asm volatile(
      "mma.sync.aligned.m16n8k8.row.col.f32.tf32.tf32.f32 "
      "{%0,%1,%2,%3}, {%4,%5,%6,%7}, {%8,%9}, {%0,%1,%2,%3};"
      : "+f"(c[0]), "+f"(c[1]), "+f"(c[2]), "+f"(c[3])
      : "r"(a[0]), "r"(a[1]), "r"(a[2]), "r"(a[3]), "r"(b[0]), "r"(b[1]));
}

__device__ __forceinline__ void mma_bf16(float* c, const uint32_t* a,
                                         const uint32_t* b) {
  asm volatile(
      "mma.sync.aligned.m16n8k16.row.col.f32.bf16.bf16.f32 "
      "{%0,%1,%2,%3}, {%4,%5,%6,%7}, {%8,%9}, {%0,%1,%2,%3};"
      : "+f"(c[0]), "+f"(c[1]), "+f"(c[2]), "+f"(c[3])
      : "r"(a[0]), "r"(a[1]), "r"(a[2]), "r"(a[3]), "r"(b[0]), "r"(b[1]));
}

__device__ __forceinline__ uint32_t bf16pack(float hi_elem, float lo_elem) {
  uint32_t r;
  asm("cvt.rn.bf16x2.f32 %0, %1, %2;" : "=r"(r) : "f"(hi_elem), "f"(lo_elem));
  return r;
}

__device__ __forceinline__ void packsplit(float x0, float x1,
                                          uint32_t& wh, uint32_t& wl) {
  wh = bf16pack(x1, x0);
  float q0 = x0 - __uint_as_float(wh << 16);
  float q1 = x1 - __uint_as_float(wh & 0xffff0000u);
  wl = bf16pack(q1, q0);
}

__device__ __forceinline__ void cp16(uint32_t dst, const void* src) {
  asm volatile("cp.async.cg.shared.global [%0], [%1], 16;"
               :: "r"(dst), "l"(src) : "memory");
}
#define CP_COMMIT() asm volatile("cp.async.commit_group;" ::: "memory")
#define CP_WAIT1() asm volatile("cp.async.wait_group 1;" ::: "memory")
#define CP_WAIT0() asm volatile("cp.async.wait_group 0;" ::: "memory")

// ---------------- 0a) pre-split x into bf16 planes -------------------------
__global__ __launch_bounds__(256) void k_split_x(const float* __restrict__ x) {
  size_t i = (size_t)blockIdx.x * 256 + threadIdx.x;   // 4 words = 8 floats
  const float* s = x + i * 8;
  float4 a = *(const float4*)s;
  float4 b = *(const float4*)(s + 4);
  uint32_t h0,l0,h1,l1,h2,l2,h3,l3;
  packsplit(a.x, a.y, h0, l0); packsplit(a.z, a.w, h1, l1);
  packsplit(b.x, b.y, h2, l2); packsplit(b.z, b.w, h3, l3);
  *(uint4*)(g_xh + i*4) = make_uint4(h0, h1, h2, h3);
  *(uint4*)(g_xl + i*4) = make_uint4(l0, l1, l2, l3);
}

// ---------------- 0b) pre-split weights ------------------------------------
__global__ __launch_bounds__(256) void k_split_w(const float* __restrict__ Ww,
                                                 const float* __restrict__ Wo) {
  size_t i = (size_t)blockIdx.x * 256 + threadIdx.x;   // 4 words
  const float* s = (i < WPM/4) ? (Ww + i*8) : (Wo + (i - WPM/4)*8);
  float4 a = *(const float4*)s;
  float4 b = *(const float4*)(s + 4);
  uint32_t h0,l0,h1,l1,h2,l2,h3,l3;
  packsplit(a.x, a.y, h0, l0); packsplit(a.z, a.w, h1, l1);
  packsplit(b.x, b.y, h2, l2); packsplit(b.z, b.w, h3, l3);
  *(uint4*)(g_wbh + i*4) = make_uint4(h0, h1, h2, h3);
  *(uint4*)(g_wbl + i*4) = make_uint4(l0, l1, l2, l3);
}

// ---------------- 1) per-token projections, 4 tokens per block -------------
__global__ __launch_bounds__(256) void k_proj_small(
    const float* __restrict__ x, const float* __restrict__ Wg,
    const float* __restrict__ Wb, const float* __restrict__ Wa,
    const float* __restrict__ dtb, const float* __restrict__ Alog) {
  __shared__ float xs[4*Dn];
  int row0 = blockIdx.x * 4;
  const float* xr = x + (size_t)row0 * Dn;
  for (int i = threadIdx.x; i < 4*Dn; i += 256) xs[i] = xr[i];
  __syncthreads();
  int h = threadIdx.x >> 5, lane = threadIdx.x & 31;
  const float* wg = Wg + h * Dn;
  const float* wb = Wb + h * Dn;
  const float* wa = Wa + h * Dn;
  float sg[4] = {0,0,0,0}, sb[4] = {0,0,0,0}, sa[4] = {0,0,0,0};
  for (int i = lane; i < Dn; i += 32) {
    float wgv = wg[i], wbv = wb[i], wav = wa[i];
#pragma unroll
    for (int tk = 0; tk < 4; tk++) {
      float xv = xs[tk*Dn + i];
      sg[tk] += xv * wgv; sb[tk] += xv * wbv; sa[tk] += xv * wav;
    }
  }
  float ss[4] = {0,0,0,0};
  for (int i = lane; i < HDn; i += 32) {
#pragma unroll
    for (int tk = 0; tk < 4; tk++) {
      float v = xs[tk*Dn + h*HDn + i]; ss[tk] += v*v;
    }
  }
#pragma unroll
  for (int tk = 0; tk < 4; tk++) {
    sg[tk] = warp_sum(sg[tk]); sb[tk] = warp_sum(sb[tk]);
    sa[tk] = warp_sum(sa[tk]); ss[tk] = warp_sum(ss[tk]);
  }
  float Ae = expf(Alog[h]);
  float dtv = dtb[h];
#pragma unroll
  for (int tk = 0; tk < 4; tk++) {
    int row = row0 + tk;
    float inv = 1.0f / fmaxf(sqrtf(ss[tk]), 1e-12f);
    int b = row >> 13, t = row & (Tn - 1);
    size_t bh = (size_t)b * Hn + h;
    float* rko = g_rk + (bh * Tn + t) * HDn;
    for (int i = lane; i < HDn; i += 32) rko[i] = xs[tk*Dn + h*HDn + i] * inv;
    if (lane == 0) {
      g_gate[bh*Tn + t] = 1.0f / (1.0f + expf(-sg[tk]));
      g_beta[bh*Tn + t] = 1.0f / (1.0f + expf(-sb[tk]));
      float z = sa[tk] + dtv;
      float sp = (z > 20.0f) ? z : log1pf(expf(z));
      g_dec[bh*Tn + t] = -Ae * sp;
    }
  }
}

// ---------------- 2) in-chunk cumsum of decay ------------------------------
__global__ void k_cumsum() {
  int idx = blockIdx.x;                  // bh*N + n
  int bh = idx >> 7, n = idx & (Nchunk - 1);
  size_t base = (size_t)bh * Tn + (size_t)n * Cn;
  float v = g_dec[base + threadIdx.x];
  int lane = threadIdx.x & 31, w = threadIdx.x >> 5;
#pragma unroll
  for (int o = 1; o < 32; o <<= 1) {
    float u = __shfl_up_sync(0xffffffffu, v, o);
    if (lane >= o) v += u;
  }
  __shared__ float tot;
  if (w == 0 && lane == 31) tot = v;
  __syncthreads();
  if (w == 1) v += tot;
  g_dec[base + threadIdx.x] = v;
}

// ---------------- 3/6) bf16 GEMM from pre-split planes, double-buffered ----
#define BSTR 20                           // plane words/row (16 + 4 pad)
#define PLANE (128*BSTR)                  // 2560 words
#define STG_W (4*PLANE)                   // Ahi, Alo, Bhi, Blo
#define GM_SMEM (2*STG_W*4)               // 81,920 B -> 2 CTAs/SM

__global__ __launch_bounds__(256, 2) void k_mma(
    const float* __restrict__ X, float* __restrict__ Out, int mode) {
  extern __shared__ uint32_t su[];
  uint32_t smu = smem_u32(su);
  int tid = threadIdx.x, wid = tid >> 5, lane = tid & 31;
  int n0 = blockIdx.x * 128;
  int m0 = blockIdx.y * 128;
  int wm = wid >> 2, wn = wid & 3;       // warp tile: rows wm*64, cols wn*32
  int g = lane >> 2, t = lane & 3;

  // device-side resolution of device-global plane pointers
  const uint32_t* Ahp = mode ? (const uint32_t*)g_oh : (const uint32_t*)g_xh;
  const uint32_t* Alp = mode ? (const uint32_t*)g_ol : (const uint32_t*)g_xl;
  const uint32_t* Bhp = (const uint32_t*)g_wbh + (size_t)mode * WPM;
  const uint32_t* Blp = (const uint32_t*)g_wbl + (size_t)mode * WPM;

  float acc[4][4][4];
#pragma unroll
  for (int mi = 0; mi < 4; mi++)
#pragma unroll
    for (int ni = 0; ni < 4; ni++)
#pragma unroll
      for (int r = 0; r < 4; r++) acc[mi][ni][r] = 0.0f;

  int row = tid >> 1, q = (tid & 1) * 8; // per plane: row, words q..q+7

  auto cp_issue = [&](int kc, int s) {
    uint32_t base = smu + (uint32_t)s * STG_W * 4;
    size_t sa = (size_t)(m0 + row) * 512 + kc * 16 + q;
    size_t sb = (size_t)(n0 + row) * 512 + kc * 16 + q;
    uint32_t d0 = base + (uint32_t)(row * BSTR + q) * 4;
    cp16(d0,                         Ahp + sa);
    cp16(d0 + 16,                    Ahp + sa + 4);
    cp16(d0 + PLANE*4,               Alp + sa);
    cp16(d0 + PLANE*4 + 16,          Alp + sa + 4);
    cp16(d0 + 2*PLANE*4,             Bhp + sb);
    cp16(d0 + 2*PLANE*4 + 16,        Bhp + sb + 4);
    cp16(d0 + 3*PLANE*4,             Blp + sb);
    cp16(d0 + 3*PLANE*4 + 16,        Blp + sb + 4);
    CP_COMMIT();
  };

  const int NC = Dn / 32;                // 32 chunks
  cp_issue(0, 0);
  for (int kc = 0; kc < NC; kc++) {
    int s = kc & 1;
    if (kc + 1 < NC) { cp_issue(kc + 1, s ^ 1); CP_WAIT1(); }
    else { CP_WAIT0(); }
    __syncthreads();                     // buffer s landed + visible
    const uint32_t* Ahi = su + s * STG_W;
    const uint32_t* Alo = Ahi + PLANE;
    const uint32_t* Bhi = Alo + PLANE;
    const uint32_t* Blo = Bhi + PLANE;
#pragma unroll
    for (int kk = 0; kk < 2; kk++) {     // K=16 per step
      uint32_t ah[4][4], al[4][4];
#pragma unroll
      for (int mi = 0; mi < 4; mi++) {
        int r0 = wm * 64 + mi * 16 + g;
        int o0 = r0 * BSTR + kk * 8 + t;
        int o1 = (r0 + 8) * BSTR + kk * 8 + t;
        ah[mi][0] = Ahi[o0]; ah[mi][1] = Ahi[o1];
        ah[mi][2] = Ahi[o0 + 4]; ah[mi][3] = Ahi[o1 + 4];
        al[mi][0] = Alo[o0]; al[mi][1] = Alo[o1];
        al[mi][2] = Alo[o0 + 4]; al[mi][3] = Alo[o1 + 4];
      }
      uint32_t bh[4][2], bl[4][2];
#pragma unroll
      for (int ni = 0; ni < 4; ni++) {
        int r0 = wn * 32 + ni * 8 + g;
        int o0 = r0 * BSTR + kk * 8 + t;
        bh[ni][0] = Bhi[o0]; bh[ni][1] = Bhi[o0 + 4];
        bl[ni][0] = Blo[o0]; bl[ni][1] = Blo[o0 + 4];
      }
#pragma unroll
      for (int mi = 0; mi < 4; mi++)
#pragma unroll
        for (int ni = 0; ni < 4; ni++) {
          mma_bf16(acc[mi][ni], ah[mi], bh[ni]);
          mma_bf16(acc[mi][ni], ah[mi], bl[ni]);
          mma_bf16(acc[mi][ni], al[mi], bh[ni]);
        }
    }
    __syncthreads();                     // mma done before buffer overwrite
  }

  int h = blockIdx.x;                     // mode 0: 128-wide n-block == head
#pragma unroll
  for (int mi = 0; mi < 4; mi++) {
#pragma unroll
    for (int rr = 0; rr < 2; rr++) {
      int m = m0 + wm * 64 + mi * 16 + g + rr * 8;
      if (mode == 0) {
        int b = m >> 13, tt = m & (Tn - 1);
        size_t bhT = ((size_t)(b * Hn + h)) * Tn + tt;
        float beta = g_beta[bhT];
        float* vout = g_v + bhT * HDn;
#pragma unroll
        for (int ni = 0; ni < 4; ni++) {
          int col = wn * 32 + ni * 8 + 2 * t;
          float2 val;
          val.x = acc[mi][ni][rr * 2 + 0] * beta;
          val.y = acc[mi][ni][rr * 2 + 1] * beta;
          *(float2*)(vout + col) = val;
        }
      } else {
#pragma unroll
        for (int ni = 0; ni < 4; ni++) {
          int ncol = n0 + wn * 32 + ni * 8 + 2 * t;
          size_t off = (size_t)m * Dn + ncol;
          float2 xv = *(const float2*)(X + off);
          float2 val;
          val.x = xv.x + acc[mi][ni][rr * 2 + 0];
          val.y = xv.y + acc[mi][ni][rr * 2 + 1];
          *(float2*)(Out + off) = val;
        }
      }
    }
  }
}

// ---------------- 4) per-chunk, all-bf16, register-resident inversion ------
#define KBS 68
#define TBS 136
#define K4_SMEM ((2*65*KBS + 64*65 + 4*64) * 4)
__global__ __launch_bounds__(256) void k_chunk() {
  extern __shared__ float smf[];
  uint32_t* kbh = (uint32_t*)smf;
  uint32_t* kbl = kbh + 65*KBS;
  uint32_t* tbh = kbh;                   // overlay (P-phase done before use)
  uint32_t* tbl = kbl;
  float* Asm   = smf + 2*65*KBS;         // 64 x 65
  float* decS  = Asm + 64*65;
  float* betaS = decS + 64;
  float* facS  = betaS + 64;
  float* beS   = facS + 64;

  int cid = blockIdx.x;                  // bh*N + n
  int bh = cid >> 7, n = cid & (Nchunk - 1);
  int tid = threadIdx.x;
  int wid = tid >> 5, lane = tid & 31;
  int g = lane >> 2, t = lane & 3;
  size_t tbase = (size_t)bh * Tn + (size_t)n * Cn;
  const float* rkG = g_rk + tbase * HDn;

  if (tid < 64) {
    float dv = g_dec[tbase + tid];
    float bv = g_beta[tbase + tid];
    decS[tid] = dv; betaS[tid] = bv; beS[tid] = bv * __expf(dv);
  }
  for (int i = tid; i < 64*64; i += 256) {
    int r1 = i >> 6, w = i & 63;
    float2 v2 = *(const float2*)(rkG + (size_t)r1 * HDn + 2*w);
    uint32_t wh, wl;
    packsplit(v2.x, v2.y, wh, wl);
    kbh[(r1+1)*KBS + w] = wh;
    kbl[(r1+1)*KBS + w] = wl;
  }
  if (tid < 64) {
    float2 v2 = (n == 0) ? make_float2(0.f, 0.f)
                         : *(const float2*)(g_rk + (tbase - 1) * HDn + 2*tid);
    uint32_t wh, wl;
    packsplit(v2.x, v2.y, wh, wl);
    kbh[tid] = wh; kbl[tid] = wl;
  }
  __syncthreads();
  if (tid < 64) facS[tid] = (tid == 0) ? 0.0f
                          : betaS[tid] * __expf(decS[tid] - decS[tid-1]);

  // ---- P[i][j] = rk_i . wk_j via bf16 mma (K=128 -> 8 k16 blocks) ---------
  int wr = wid >> 2, wc = wid & 3;
  float pacc[2][2][4];
#pragma unroll
  for (int mi = 0; mi < 2; mi++)
#pragma unroll
    for (int ni = 0; ni < 2; ni++)
#pragma unroll
      for (int r = 0; r < 4; r++) pacc[mi][ni][r] = 0.0f;

#pragma unroll 1
  for (int ks = 0; ks < 8; ks++) {
    int w1 = ks*8 + t;
    uint32_t ah[2][4], al[2][4];
#pragma unroll
    for (int mi = 0; mi < 2; mi++) {
      int r0 = 1 + wr*32 + mi*16 + g;
      ah[mi][0] = kbh[r0*KBS + w1];     ah[mi][1] = kbh[(r0+8)*KBS + w1];
      ah[mi][2] = kbh[r0*KBS + w1 + 4]; ah[mi][3] = kbh[(r0+8)*KBS + w1 + 4];
      al[mi][0] = kbl[r0*KBS + w1];     al[mi][1] = kbl[(r0+8)*KBS + w1];
      al[mi][2] = kbl[r0*KBS + w1 + 4]; al[mi][3] = kbl[(r0+8)*KBS + w1 + 4];
    }
    uint32_t bhf[2][2], blf[2][2];
#pragma unroll
    for (int ni = 0; ni < 2; ni++) {
      int nr = wc*16 + ni*8 + g;
      bhf[ni][0] = kbh[nr*KBS + w1]; bhf[ni][1] = kbh[nr*KBS + w1 + 4];
      blf[ni][0] = kbl[nr*KBS + w1]; blf[ni][1] = kbl[nr*KBS + w1 + 4];
    }
#pragma unroll
    for (int mi = 0; mi < 2; mi++)
#pragma unroll
      for (int ni = 0; ni < 2; ni++) {
        mma_bf16(pacc[mi][ni], ah[mi], bhf[ni]);
        mma_bf16(pacc[mi][ni], ah[mi], blf[ni]);
        mma_bf16(pacc[mi][ni], al[mi], bhf[ni]);
      }
  }

  float* attnOut = g_attn + (size_t)cid * 4096;
#pragma unroll
  for (int mi = 0; mi < 2; mi++)
#pragma unroll
    for (int ni = 0; ni < 2; ni++)
#pragma unroll
      for (int r = 0; r < 4; r++) {
        int i = wr*32 + mi*16 + g + ((r & 2) ? 8 : 0);
        int j = wc*16 + ni*8 + 2*t + (r & 1);
        float aval = 0.0f;
        if (i >= j) {
          aval = pacc[mi][ni][r] * __expf(decS[i] - decS[j]);
          Asm[i*65 + j] = aval;
        }
        attnOut[i*64 + j] = aval;
      }
  __syncthreads();

  // M^T into Asm upper
  for (int idx = tid; idx < 4096; idx += 256) {
    int i = idx >> 6, j = idx & 63;
    if (i > j) Asm[j*65 + i] = Asm[(i-1)*65 + j] * facS[i];
  }
  __syncthreads();

  // register-resident forward substitution: X = (I+M)^-1
  {
    int c0 = wid * 8;
    int r0 = 2 * lane, r1 = r0 + 1;
    float X0[8], X1[8];
#pragma unroll
    for (int k = 0; k < 8; k++) {
      X0[k] = (r0 == c0 + k) ? 1.0f : 0.0f;
      X1[k] = (r1 == c0 + k) ? 1.0f : 0.0f;
    }
    for (int i = 0; i < 63; i++) {
      float xi[8];
      int src = i >> 1;
      if (i & 1) {
#pragma unroll
        for (int k = 0; k < 8; k++) xi[k] = __shfl_sync(0xffffffffu, X1[k], src);
      } else {
#pragma unroll
        for (int k = 0; k < 8; k++) xi[k] = __shfl_sync(0xffffffffu, X0[k], src);
      }
      if (r0 > i) {
        float m = Asm[i*65 + r0];
#pragma unroll
        for (int k = 0; k < 8; k++) X0[k] -= m * xi[k];
      }
      if (r1 > i) {
        float m = Asm[i*65 + r1];
#pragma unroll
        for (int k = 0; k < 8; k++) X1[k] -= m * xi[k];
      }
    }
    __syncthreads();
#pragma unroll
    for (int k = 0; k < 8; k++) {
      Asm[r0*65 + c0 + k] = X0[k];
      Asm[r1*65 + c0 + k] = X1[k];
    }
  }

  // stage tb planes with scaled wk (transposed)
  for (int i = tid; i < 32*128; i += 256) {
    int w = i >> 7, d = i & 127;
    int j0 = 2*w;
    float x0 = (j0 == 0)
        ? ((n == 0) ? 0.0f : g_rk[(tbase - 1) * HDn + d])
        : rkG[(size_t)(j0 - 1) * HDn + d];
    float x1 = rkG[(size_t)j0 * HDn + d];
    x0 *= beS[j0]; x1 *= beS[j0 + 1];
    uint32_t wh, wl;
    packsplit(x0, x1, wh, wl);
    tbh[w*TBS + d] = wh; tbl[w*TBS + d] = wl;
  }
  __syncthreads();

  int wr2 = wid >> 1, wc2 = wid & 1;
  auto triMulBf = [&](float* outp) {
    float cacc[8][4];
#pragma unroll
    for (int ni = 0; ni < 8; ni++)
#pragma unroll
      for (int r = 0; r < 4; r++) cacc[ni][r] = 0.0f;
#pragma unroll 1
    for (int ks = 0; ks < 4; ks++) {
      int w1 = ks*8 + t;
      int r0 = wr2*16 + g;
      uint32_t ah4[4], al4[4];
      packsplit(Asm[r0*65 + 2*w1],       Asm[r0*65 + 2*w1 + 1],     ah4[0], al4[0]);
      packsplit(Asm[(r0+8)*65 + 2*w1],   Asm[(r0+8)*65 + 2*w1 + 1], ah4[1], al4[1]);
      packsplit(Asm[r0*65 + 2*w1 + 8],   Asm[r0*65 + 2*w1 + 9],     ah4[2], al4[2]);
      packsplit(Asm[(r0+8)*65 + 2*w1+8], Asm[(r0+8)*65 + 2*w1 + 9], ah4[3], al4[3]);
#pragma unroll
      for (int ni = 0; ni < 8; ni++) {
        int nn = wc2*64 + ni*8 + g;
        uint32_t b2h[2], b2l[2];
        b2h[0] = tbh[w1*TBS + nn]; b2h[1] = tbh[(w1+4)*TBS + nn];
        b2l[0] = tbl[w1*TBS + nn]; b2l[1] = tbl[(w1+4)*TBS + nn];
        mma_bf16(cacc[ni], ah4, b2h);
        mma_bf16(cacc[ni], ah4, b2l);
        mma_bf16(cacc[ni], al4, b2h);
      }
    }
#pragma unroll
    for (int ni = 0; ni < 8; ni++)
#pragma unroll
      for (int rr = 0; rr < 2; rr++) {
        int c = wr2*16 + g + rr*8;
        int d = wc2*64 + ni*8 + 2*t;
        float2 val;
        val.x = cacc[ni][rr*2 + 0];
        val.y = cacc[ni][rr*2 + 1];
        *(float2*)(outp + (size_t)c*HDn + d) = val;
      }
  };

  triMulBf(g_wkcd + tbase * HDn);
  __syncthreads();

  {
    const float* vG = g_v + tbase * HDn;
    for (int i = tid; i < 32*128; i += 256) {
      int w = i >> 7, d = i & 127;
      float x0 = vG[(size_t)(2*w) * HDn + d];
      float x1 = vG[(size_t)(2*w + 1) * HDn + d];
      uint32_t wh, wl;
      packsplit(x0, x1, wh, wl);
      tbh[w*TBS + d] = wh; tbl[w*TBS + d] = wl;
    }
  }
  __syncthreads();

  triMulBf(g_v + tbase * HDn);
}

// ---------------- 5) inter-chunk recurrence, tensorized (tf32) -------------
#define RS 132
#define SS 40
#define ATS 68
#define K5_SMEM ((3*128*SS + 4*64*SS + 64*ATS + 64*RS + 65*RS + 2*64) * 4)
__global__ __launch_bounds__(256) void k_recur() {
  extern __shared__ float smf[];
  float* S      = smf;                   // 128 x 40 fp32
  float* S_hi   = S     + 128*SS;
  float* S_lo   = S_hi  + 128*SS;
  float* vn_hi  = S_lo  + 128*SS;
  float* vn_lo  = vn_hi + 64*SS;
  float* vns_hi = vn_lo + 64*SS;
  float* vns_lo = vns_hi+ 64*SS;
  float* attnS  = vns_lo+ 64*SS;         // 64 x 68
  float* bufA   = attnS + 64*ATS;        // 64 x 132 (wkcd)
  float* bufB   = bufA  + 64*RS;         // 65 x 132 (row0=wk0, 1..64=rk)
  float* edwS   = bufB  + 65*RS;
  float* edcS   = edwS  + 64;

  uint32_t smb = smem_u32(smf);
  int blk = blockIdx.x;                  // bh*4 + eg
  int bh = blk >> 2, eg = blk & 3;
  int e0 = eg * 32;
  int b = bh >> 3, h = bh & 7;
  int tid = threadIdx.x;
  int wid = tid >> 5, lane = tid & 31;
  int g = lane >> 2, t = lane & 3;

  for (int i = tid; i < 3*128*SS; i += 256) S[i] = 0.0f;
  __syncthreads();

  uint32_t sm_attn = smb + (uint32_t)((attnS - smf) * 4);
  uint32_t sm_bufA = smb + (uint32_t)((bufA - smf) * 4);
  uint32_t sm_bufB = smb + (uint32_t)((bufB - smf) * 4);

  for (int n = 0; n < Nchunk; n++) {
    size_t tbase = (size_t)bh * Tn + (size_t)n * Cn;
    {
      const float* aG = g_attn + ((size_t)bh * Nchunk + n) * 4096;
#pragma unroll
      for (int q = 0; q < 4; q++) {
        int idx = q * 256 + tid;
        int r = idx >> 4, c4 = idx & 15;
        cp16(sm_attn + (uint32_t)(r * ATS + c4 * 4) * 4, aG + r * 64 + c4 * 4);
      }
      const float* wkcdG = g_wkcd + tbase * HDn;
      const float* rkG = g_rk + tbase * HDn;
#pragma unroll
      for (int q = 0; q < 8; q++) {
        int idx = q * 256 + tid;
        int r = idx >> 5, c4 = idx & 31;
        cp16(sm_bufA + (uint32_t)(r * RS + c4 * 4) * 4,
             wkcdG + (size_t)r * HDn + c4 * 4);
        cp16(sm_bufB + (uint32_t)((r + 1) * RS + c4 * 4) * 4,
             rkG + (size_t)r * HDn + c4 * 4);
      }
      if (tid < 32) {
        if (n == 0) {
          float4 z = make_float4(0.f, 0.f, 0.f, 0.f);
          *(float4*)(bufB + tid * 4) = z;
        } else {
          cp16(sm_bufB + (uint32_t)(tid * 4) * 4,
               g_rk + (tbase - 1) * HDn + tid * 4);
        }
      }
      if (tid < 64) {
        float dv = g_dec[tbase + tid];
        float d63 = g_dec[tbase + 63];
        edcS[tid] = __expf(dv);
        edwS[tid] = __expf(d63 - dv);
      }
      CP_COMMIT(); CP_WAIT0();
    }
    __syncthreads();

    float acc[4][4];
    int w4 = wid & 3;
    int m0 = w4 * 16;
    bool isV = (wid < 4);
    if (isV) {
      const float* vG = g_v + tbase * HDn;
#pragma unroll
      for (int ni = 0; ni < 4; ni++) {
        int e = ni * 8 + 2 * t;
        float2 p0 = *(const float2*)(vG + (size_t)(m0 + g) * HDn + e0 + e);
        float2 p1 = *(const float2*)(vG + (size_t)(m0 + 8 + g) * HDn + e0 + e);
        acc[ni][0] = p0.x; acc[ni][1] = p0.y;
        acc[ni][2] = p1.x; acc[ni][3] = p1.y;
      }
    } else {
#pragma unroll
      for (int ni = 0; ni < 4; ni++)
#pragma unroll
        for (int r = 0; r < 4; r++) acc[ni][r] = 0.0f;
    }
    {
      const float* Abuf = isV ? bufA : (bufB + RS);
      float sgn = isV ? -1.0f : 1.0f;
#pragma unroll 2
      for (int ks = 0; ks < 16; ks++) {
        int k0 = ks * 8;
        uint32_t ah[4], al[4];
        split2(sgn * Abuf[(m0 + g) * RS + k0 + t],         ah[0], al[0]);
        split2(sgn * Abuf[(m0 + 8 + g) * RS + k0 + t],     ah[1], al[1]);
        split2(sgn * Abuf[(m0 + g) * RS + k0 + t + 4],     ah[2], al[2]);
        split2(sgn * Abuf[(m0 + 8 + g) * RS + k0 + t + 4], ah[3], al[3]);
#pragma unroll
        for (int ni = 0; ni < 4; ni++) {
          int nn = ni * 8 + g;
          uint32_t bh2[2], bl2[2];
          bh2[0] = __float_as_uint(S_hi[(k0 + t) * SS + nn]);
          bh2[1] = __float_as_uint(S_hi[(k0 + t + 4) * SS + nn]);
          bl2[0] = __float_as_uint(S_lo[(k0 + t) * SS + nn]);
          bl2[1] = __float_as_uint(S_lo[(k0 + t + 4) * SS + nn]);
          mma_tf32(acc[ni], ah, bh2);
          mma_tf32(acc[ni], ah, bl2);
          mma_tf32(acc[ni], al, bh2);
        }
      }
    }
    if (isV) {
#pragma unroll
      for (int ni = 0; ni < 4; ni++)
#pragma unroll
        for (int r = 0; r < 4; r++) {
          int c = m0 + g + ((r & 2) ? 8 : 0);
          int e = ni * 8 + 2 * t + (r & 1);
          float v = acc[ni][r];
          uint32_t hh, ll;
          split2(v, hh, ll);
          vn_hi[c * SS + e] = __uint_as_float(hh);
          vn_lo[c * SS + e] = __uint_as_float(ll);
          float vs = v * edwS[c];
          split2(vs, hh, ll);
          vns_hi[c * SS + e] = __uint_as_float(hh);
          vns_lo[c * SS + e] = __uint_as_float(ll);
        }
    } else {
#pragma unroll
      for (int ni = 0; ni < 4; ni++) {
        acc[ni][0] *= edcS[m0 + g];     acc[ni][1] *= edcS[m0 + g];
        acc[ni][2] *= edcS[m0 + 8 + g]; acc[ni][3] *= edcS[m0 + 8 + g];
      }
    }
    __syncthreads();

    if (!isV) {
#pragma unroll 1
      for (int ks = 0; ks < 8; ks++) {
        int k0 = ks * 8;
        uint32_t ah[4], al[4];
        split2(attnS[(m0 + g) * ATS + k0 + t],         ah[0], al[0]);
        split2(attnS[(m0 + 8 + g) * ATS + k0 + t],     ah[1], al[1]);
        split2(attnS[(m0 + g) * ATS + k0 + t + 4],     ah[2], al[2]);
        split2(attnS[(m0 + 8 + g) * ATS + k0 + t + 4], ah[3], al[3]);
#pragma unroll
        for (int ni = 0; ni < 4; ni++) {
          int nn = ni * 8 + g;
          uint32_t bh2[2], bl2[2];
          bh2[0] = __float_as_uint(vn_hi[(k0 + t) * SS + nn]);
          bh2[1] = __float_as_uint(vn_hi[(k0 + t + 4) * SS + nn]);
          bl2[0] = __float_as_uint(vn_lo[(k0 + t) * SS + nn]);
          bl2[1] = __float_as_uint(vn_lo[(k0 + t + 4) * SS + nn]);
          mma_tf32(acc[ni], ah, bh2);
          mma_tf32(acc[ni], ah, bl2);
          mma_tf32(acc[ni], al, bh2);
        }
      }
      // gated store directly as bf16 hi/lo planes (adjacent d-pairs in regs)
#pragma unroll
      for (int rr = 0; rr < 2; rr++) {
        int c = m0 + g + rr * 8;
        int tg = n * Cn + c;
        float gate = g_gate[(size_t)bh * Tn + tg];
        size_t wbase = ((size_t)b * Tn + tg) * 512 + (h * HDn + e0) / 2;
#pragma unroll
        for (int ni = 0; ni < 4; ni++) {
          float vx = acc[ni][rr * 2 + 0] * gate;
          float vy = acc[ni][rr * 2 + 1] * gate;
          uint32_t wh, wl;
          packsplit(vx, vy, wh, wl);
          g_oh[wbase + ni * 4 + t] = wh;
          g_ol[wbase + ni * 4 + t] = wl;
        }
      }
    } else {
      int m0u = w4 * 32;
      float acc2[2][4][4];
#pragma unroll
      for (int mi = 0; mi < 2; mi++)
#pragma unroll
        for (int ni = 0; ni < 4; ni++)
#pragma unroll
          for (int r = 0; r < 4; r++) acc2[mi][ni][r] = 0.0f;
#pragma unroll 1
      for (int ks = 0; ks < 8; ks++) {
        int k0 = ks * 8;
        uint32_t ah[2][4], al[2][4];
#pragma unroll
        for (int mi = 0; mi < 2; mi++) {
          int mm = m0u + mi * 16 + g;
          split2(bufB[(k0 + t) * RS + mm],         ah[mi][0], al[mi][0]);
          split2(bufB[(k0 + t) * RS + mm + 8],     ah[mi][1], al[mi][1]);
          split2(bufB[(k0 + t + 4) * RS + mm],     ah[mi][2], al[mi][2]);
          split2(bufB[(k0 + t + 4) * RS + mm + 8], ah[mi][3], al[mi][3]);
        }
#pragma unroll
        for (int ni = 0; ni < 4; ni++) {
          int nn = ni * 8 + g;
          uint32_t bh2[2], bl2[2];
          bh2[0] = __float_as_uint(vns_hi[(k0 + t) * SS + nn]);
          bh2[1] = __float_as_uint(vns_hi[(k0 + t + 4) * SS + nn]);
          bl2[0] = __float_as_uint(vns_lo[(k0 + t) * SS + nn]);
          bl2[1] = __float_as_uint(vns_lo[(k0 + t + 4) * SS + nn]);
#pragma unroll
          for (int mi = 0; mi < 2; mi++) {
            mma_tf32(acc2[mi][ni], ah[mi], bh2);
            mma_tf32(acc2[mi][ni], ah[mi], bl2);
            mma_tf32(acc2[mi][ni], al[mi], bh2);
          }
        }
      }
      float gl = edcS[63];
#pragma unroll
      for (int mi = 0; mi < 2; mi++)
#pragma unroll
        for (int ni = 0; ni < 4; ni++)
#pragma unroll
          for (int r = 0; r < 4; r++) {
            int d = m0u + mi * 16 + g + ((r & 2) ? 8 : 0);
            int e = ni * 8 + 2 * t + (r & 1);
            float sNew = gl * S[d * SS + e] + acc2[mi][ni][r];
            S[d * SS + e] = sNew;
            uint32_t hh, ll;
            split2(sNew, hh, ll);
            S_hi[d * SS + e] = __uint_as_float(hh);
            S_lo[d * SS + e] = __uint_as_float(ll);
          }
    }
    __syncthreads();
  }
}

// ---------------------------------------------------------------------------
extern "C" void kernel_launch(void* const* d_in, const int* in_sizes, int n_in,
                              void* d_out, int out_size) {
  (void)in_sizes; (void)n_in; (void)out_size;
  const float* x    = (const float*)d_in[0];
  const float* Ww   = (const float*)d_in[1];
  const float* Wg   = (const float*)d_in[2];
  const float* Wo   = (const float*)d_in[3];
  const float* Wb   = (const float*)d_in[4];
  const float* Wa   = (const float*)d_in[5];
  const float* dtb  = (const float*)d_in[6];
  const float* Alog = (const float*)d_in[7];
  float* out = (float*)d_out;

  cudaFuncSetAttribute(k_mma, cudaFuncAttributeMaxDynamicSharedMemorySize, GM_SMEM);
  cudaFuncSetAttribute(k_chunk, cudaFuncAttributeMaxDynamicSharedMemorySize, K4_SMEM);
  cudaFuncSetAttribute(k_recur, cudaFuncAttributeMaxDynamicSharedMemorySize, K5_SMEM);

  k_split_x<<<BTn*512/4/256, 256>>>(x);
  k_split_w<<<2*WPM/4/256, 256>>>(Ww, Wo);
  k_proj_small<<<BTn/4, 256>>>(x, Wg, Wb, Wa, dtb, Alog);
  k_cumsum<<<BHn * Nchunk, 64>>>();
  k_mma<<<dim3(Dn/128, BTn/128), 256, GM_SMEM>>>(x, nullptr, 0);
  k_chunk<<<BHn * Nchunk, 256, K4_SMEM>>>();
  k_recur<<<BHn * 4, 256, K5_SMEM>>>();
  k_mma<<<dim3(Dn/128, BTn/128), 256, GM_SMEM>>>(x, out, 1);
}